// round 16
// baseline (speedup 1.0000x reference)
#include <cuda_runtime.h>
#include <cuda_bf16.h>
#include <cstdint>
#include <cmath>

#define B_  256
#define T_  128
#define D_  256
#define H1  512
#define G1  (4*H1)
#define H2  1024
#define G2  (4*H2)

// scratch
__device__ unsigned g_bars[16];
__device__ __nv_bfloat16 g_igf [(size_t)T_*B_*G1];
__device__ __nv_bfloat16 g_igb [(size_t)T_*B_*G1];
__device__ __nv_bfloat16 g_igs [(size_t)T_*B_*G2];
__device__ __nv_bfloat16 g_xb  [(size_t)B_*T_*D_];
__device__ __nv_bfloat16 g_comb[(size_t)T_*B_*(2*H1)];
__device__ __nv_bfloat16 g_zero[B_*H2];
__device__ __nv_bfloat16 g_h2a [B_*H2];
__device__ __nv_bfloat16 g_h2b [B_*H2];
__device__ __nv_bfloat16 g_wfih[(size_t)G1*D_];
__device__ __nv_bfloat16 g_wbih[(size_t)G1*D_];
__device__ __nv_bfloat16 g_wsih[(size_t)G2*(2*H1)];
__device__ __nv_bfloat16 g_wfhh[(size_t)G1*H1];
__device__ __nv_bfloat16 g_wbhh[(size_t)G1*H1];
__device__ __nv_bfloat16 g_wshh[(size_t)G2*H2];

__device__ __forceinline__ void mma_bf16(float& d0, float& d1, float& d2, float& d3,
                                         uint32_t a0, uint32_t a1, uint32_t a2, uint32_t a3,
                                         uint32_t b0, uint32_t b1) {
    asm volatile("mma.sync.aligned.m16n8k16.row.col.f32.bf16.bf16.f32 "
        "{%0,%1,%2,%3}, {%4,%5,%6,%7}, {%8,%9}, {%0,%1,%2,%3};\n"
        : "+f"(d0), "+f"(d1), "+f"(d2), "+f"(d3)
        : "r"(a0), "r"(a1), "r"(a2), "r"(a3), "r"(b0), "r"(b1));
}
__device__ __forceinline__ float tanh_ap(float x) {
    float y; asm("tanh.approx.f32 %0, %1;" : "=f"(y) : "f"(x)); return y;
}
__device__ __forceinline__ float sigm_ap(float x) { return 0.5f * tanh_ap(0.5f * x) + 0.5f; }
__device__ __forceinline__ float sigm_ex(float x) { return 1.0f / (1.0f + expf(-x)); }

// Release/acquire group barrier: call with all threads; h-stores must precede.
__device__ __forceinline__ void group_barrier(unsigned* bar, unsigned target, int tid) {
    __syncthreads();
    if (tid == 0) {
        asm volatile("red.release.gpu.global.add.u32 [%0], %1;" :: "l"(bar), "r"(1u) : "memory");
        unsigned v;
        while (true) {
            asm volatile("ld.acquire.gpu.global.u32 %0, [%1];" : "=r"(v) : "l"(bar) : "memory");
            if ((int)(v - target) >= 0) break;
            __nanosleep(32);
        }
    }
    __syncthreads();
}

// ---------------------------------------------------------------------------
struct SegT { const float* s; __nv_bfloat16* d; int n; };
struct Seg7 { SegT seg[7]; };

__global__ void f2bf_all(Seg7 p) {
    int stride = gridDim.x * blockDim.x;
    int base = blockIdx.x * blockDim.x + threadIdx.x;
#pragma unroll
    for (int k = 0; k < 7; k++) {
        const float* s = p.seg[k].s;
        __nv_bfloat16* d = p.seg[k].d;
        int n = p.seg[k].n;
        for (int i = base; i < n; i += stride) d[i] = __float2bfloat16(s[i]);
    }
}

// ---------------------------------------------------------------------------
// bf16 GEMM, bf16 output (unchanged).
// ---------------------------------------------------------------------------
__global__ void __launch_bounds__(256, 2) gemm_bf16_nt(
    const __nv_bfloat16* __restrict__ A, const __nv_bfloat16* __restrict__ W,
    __nv_bfloat16* __restrict__ out, int M, int N, int K, int remap)
{
    __shared__ uint32_t As[128][20];
    __shared__ uint32_t Bs[128][20];
    const int tid = threadIdx.x, lane = tid & 31, warp = tid >> 5;
    const int gid = lane >> 2, tig = lane & 3;
    const int wm = warp >> 2, wn = warp & 3;
    const int bm0 = blockIdx.y * 128, bn0 = blockIdx.x * 128;

    float acc[4][4][4];
#pragma unroll
    for (int a = 0; a < 4; a++)
#pragma unroll
        for (int b = 0; b < 4; b++)
#pragma unroll
            for (int c = 0; c < 4; c++) acc[a][b][c] = 0.f;

    const int kIters = K / 32;
    uint4 pa[2], pb[2];
#pragma unroll
    for (int j = 0; j < 2; j++) { int i = tid + j*256, r = i>>2, c = i&3;
        pa[j] = *(const uint4*)(A + (size_t)(bm0+r)*K + c*8);
        pb[j] = *(const uint4*)(W + (size_t)(bn0+r)*K + c*8); }

    for (int kt = 0; kt < kIters; kt++) {
#pragma unroll
        for (int j = 0; j < 2; j++) { int i = tid + j*256, r = i>>2, c = i&3;
            As[r][c*4+0]=pa[j].x; As[r][c*4+1]=pa[j].y; As[r][c*4+2]=pa[j].z; As[r][c*4+3]=pa[j].w;
            Bs[r][c*4+0]=pb[j].x; Bs[r][c*4+1]=pb[j].y; Bs[r][c*4+2]=pb[j].z; Bs[r][c*4+3]=pb[j].w; }
        __syncthreads();
        if (kt + 1 < kIters) {
            int k0 = (kt+1)*32;
#pragma unroll
            for (int j = 0; j < 2; j++) { int i = tid + j*256, r = i>>2, c = i&3;
                pa[j] = *(const uint4*)(A + (size_t)(bm0+r)*K + k0 + c*8);
                pb[j] = *(const uint4*)(W + (size_t)(bn0+r)*K + k0 + c*8); }
        }
#pragma unroll
        for (int kc = 0; kc < 2; kc++) {
            uint32_t af[4][4];
#pragma unroll
            for (int mt = 0; mt < 4; mt++) {
                int r = wm*64 + mt*16;
                af[mt][0] = As[r+gid  ][kc*8+tig  ];
                af[mt][1] = As[r+gid+8][kc*8+tig  ];
                af[mt][2] = As[r+gid  ][kc*8+tig+4];
                af[mt][3] = As[r+gid+8][kc*8+tig+4];
            }
#pragma unroll
            for (int nt = 0; nt < 4; nt++) {
                int cc = wn*32 + nt*8;
                uint32_t b0 = Bs[cc+gid][kc*8+tig  ];
                uint32_t b1 = Bs[cc+gid][kc*8+tig+4];
#pragma unroll
                for (int mt = 0; mt < 4; mt++)
                    mma_bf16(acc[mt][nt][0],acc[mt][nt][1],acc[mt][nt][2],acc[mt][nt][3],
                             af[mt][0],af[mt][1],af[mt][2],af[mt][3], b0, b1);
            }
        }
        __syncthreads();
    }
#pragma unroll
    for (int mt = 0; mt < 4; mt++)
#pragma unroll
        for (int half = 0; half < 2; half++) {
            int m = bm0 + wm*64 + mt*16 + gid + half*8;
            int orow;
            if (remap == 0) orow = m;
            else { int t = m % T_, b = m / T_;
                   orow = ((remap == 1) ? t : (T_-1-t)) * B_ + b; }
            __nv_bfloat16* op = out + (size_t)orow*N + bn0 + wn*32 + 2*tig;
#pragma unroll
            for (int nt = 0; nt < 4; nt++) {
                __nv_bfloat162 v;
                v.x = __float2bfloat16(acc[mt][nt][half*2+0]);
                v.y = __float2bfloat16(acc[mt][nt][half*2+1]);
                *(__nv_bfloat162*)(op + nt*8) = v;
            }
        }
}

// ---------------------------------------------------------------------------
// Layer-1 persistent scan (as R13) + release/acquire barrier.
// grid = 128 = dir(2) x mb(4) x jt(16); 512 thr; K-split warps.
// ---------------------------------------------------------------------------
#define S1_ASH (128*260)
#define S1_SMEM (((128*260)+(64*260))*4)

__global__ void __launch_bounds__(512, 1) lstm_scan1(
    const __nv_bfloat16* __restrict__ Whh_f, const __nv_bfloat16* __restrict__ Whh_b,
    const float* __restrict__ bias_f, const float* __restrict__ bias_b,
    const __nv_bfloat16* __restrict__ igf, const __nv_bfloat16* __restrict__ igb,
    const __nv_bfloat16* __restrict__ h0, __nv_bfloat16* __restrict__ hist,
    unsigned* __restrict__ bars)
{
    extern __shared__ uint32_t dsm[];
    uint32_t* wsh = dsm;
    uint32_t* ash = dsm + S1_ASH;
    float*    gsh = (float*)(dsm + S1_ASH);   // [2][64][129]
    __shared__ float bsh[128];

    const int tid = threadIdx.x, lane = tid & 31, warp = tid >> 5;
    const int gid = lane >> 2, tig = lane & 3;
    const int kh = warp >> 3, mq = (warp >> 2) & 1, g = warp & 3;

    const int dir = blockIdx.x >> 6;
    const int rem = blockIdx.x & 63;
    const int m0  = (rem >> 4) * 64;
    const int j0  = (rem & 15) * 32;
    unsigned* bar = bars + (dir*4 + (rem >> 4));

    const __nv_bfloat16* Whh = dir ? Whh_b : Whh_f;
    const float* bias = dir ? bias_b : bias_f;
    const __nv_bfloat16* ig = dir ? igb : igf;
    const int hstride = 2*H1, hdiroff = dir*H1;

#pragma unroll
    for (int j = 0; j < 16; j++) {
        int idx = j*512 + tid, n = idx >> 6, c = idx & 63;
        int grow = (n>>5)*H1 + j0 + (n&31);
        ((uint4*)(wsh + n*260))[c] = *(const uint4*)(Whh + (size_t)grow*H1 + c*8);
    }
    if (tid < 128) bsh[tid] = bias[(tid>>5)*H1 + j0 + (tid&31)];
    __syncthreads();

    float c_reg[4] = {0.f,0.f,0.f,0.f};
    const int erow = tid >> 5, ejj = tid & 31;
    const int ej = j0 + ejj;

    for (int t = 0; t < T_; t++) {
        const __nv_bfloat16* hp = (t == 0) ? h0 : hist + (size_t)(t-1)*B_*(2*H1);
        __nv_bfloat16* hn = hist + (size_t)t*B_*(2*H1);

        float pf[4][4];
#pragma unroll
        for (int s = 0; s < 4; s++) {
            int b = m0 + erow + s*16;
            size_t igbase = ((size_t)t*B_ + b) * (size_t)G1;
#pragma unroll
            for (int gg2 = 0; gg2 < 4; gg2++)
                pf[s][gg2] = __bfloat162float(ig[igbase + gg2*H1 + ej]);
        }

#pragma unroll
        for (int j = 0; j < 8; j++) {
            int idx = j*512 + tid, r = idx >> 6, c = idx & 63;
            uint4 v = __ldcg((const uint4*)(hp + (size_t)(m0+r)*hstride + hdiroff + c*8));
            ((uint4*)(ash + r*260))[c] = v;
        }
        __syncthreads();

        float acc[2][4][4];
#pragma unroll
        for (int a = 0; a < 2; a++)
#pragma unroll
            for (int b = 0; b < 4; b++)
#pragma unroll
                for (int c = 0; c < 4; c++) acc[a][b][c] = 0.f;

#pragma unroll 4
        for (int kc = 0; kc < 16; kc++) {
            int kb = kh*128 + kc*8;
            uint32_t af[2][4];
#pragma unroll
            for (int mt = 0; mt < 2; mt++) {
                int r = mq*32 + mt*16;
                af[mt][0] = ash[(r+gid  )*260 + kb+tig  ];
                af[mt][1] = ash[(r+gid+8)*260 + kb+tig  ];
                af[mt][2] = ash[(r+gid  )*260 + kb+tig+4];
                af[mt][3] = ash[(r+gid+8)*260 + kb+tig+4];
            }
#pragma unroll
            for (int nt = 0; nt < 4; nt++) {
                int br = g*32 + nt*8 + gid;
                uint32_t b0 = wsh[br*260 + kb+tig  ];
                uint32_t b1 = wsh[br*260 + kb+tig+4];
#pragma unroll
                for (int mt = 0; mt < 2; mt++)
                    mma_bf16(acc[mt][nt][0],acc[mt][nt][1],acc[mt][nt][2],acc[mt][nt][3],
                             af[mt][0],af[mt][1],af[mt][2],af[mt][3], b0, b1);
            }
        }
        __syncthreads();   // mmas done -> overwrite ash with gsh planes

        float* gp = gsh + kh*64*129;
#pragma unroll
        for (int mt = 0; mt < 2; mt++) {
            int rb = mq*32 + mt*16;
#pragma unroll
            for (int nt = 0; nt < 4; nt++) {
                int col = g*32 + nt*8 + 2*tig;
                gp[(rb+gid  )*129 + col  ] = acc[mt][nt][0];
                gp[(rb+gid  )*129 + col+1] = acc[mt][nt][1];
                gp[(rb+gid+8)*129 + col  ] = acc[mt][nt][2];
                gp[(rb+gid+8)*129 + col+1] = acc[mt][nt][3];
            }
        }
        __syncthreads();

#pragma unroll
        for (int s = 0; s < 4; s++) {
            int row = erow + s*16;
            int b = m0 + row;
            float gi = gsh[row*129 +      ejj] + gsh[64*129 + row*129 +      ejj] + pf[s][0] + bsh[      ejj];
            float gf = gsh[row*129 + 32 + ejj] + gsh[64*129 + row*129 + 32 + ejj] + pf[s][1] + bsh[ 32 + ejj];
            float gg = gsh[row*129 + 64 + ejj] + gsh[64*129 + row*129 + 64 + ejj] + pf[s][2] + bsh[ 64 + ejj];
            float go = gsh[row*129 + 96 + ejj] + gsh[64*129 + row*129 + 96 + ejj] + pf[s][3] + bsh[ 96 + ejj];
            float cn = sigm_ap(gf)*c_reg[s] + sigm_ap(gi)*tanh_ap(gg);
            c_reg[s] = cn;
            hn[(size_t)b*hstride + hdiroff + ej] = __float2bfloat16(sigm_ap(go)*tanh_ap(cn));
        }

        group_barrier(bar, 16u*(unsigned)(t+1), tid);
    }
}

// ---------------------------------------------------------------------------
// Layer-2 persistent scan, R15: weights RESIDENT in smem (128 KB), h streamed.
// grid = 128 = mb(2) x jt(64); block owns 128 batch x 16 j x 4 gates.
// 16 warps = kh(2) x mq(4) x ng(2); warp tile 32x32; kh partial sums combined
// in one gsh plane (kh0 stores, kh1 adds). h streamed in 16 x 64-k slabs,
// double-buffered (1 sync each).
// dyn smem (u32): wsh[64][516] | hs[2][128][36] | gsh[128][65] f32.
// ---------------------------------------------------------------------------
#define S2_HS  (64*516)
#define S2_GSH (S2_HS + 2*128*36)
#define S2_SMEM ((64*516 + 2*128*36 + 128*65)*4)

__global__ void __launch_bounds__(512, 1) lstm_scan2(
    const __nv_bfloat16* __restrict__ Whh,
    const float* __restrict__ bias, const __nv_bfloat16* __restrict__ ig,
    const __nv_bfloat16* __restrict__ h0,
    __nv_bfloat16* __restrict__ h2a, __nv_bfloat16* __restrict__ h2b,
    unsigned* __restrict__ bars)
{
    extern __shared__ uint32_t dsm[];
    uint32_t* wsh = dsm;                    // [64][516]
    uint32_t* hs  = dsm + S2_HS;            // [2][128][36]
    float*    gsh = (float*)(dsm + S2_GSH); // [128][65]
    __shared__ float bsh[64];

    const int tid = threadIdx.x, lane = tid & 31, warp = tid >> 5;
    const int gid = lane >> 2, tig = lane & 3;
    const int kh = warp >> 3, mq = (warp >> 1) & 3, ng = warp & 1;

    const int mb = blockIdx.x >> 6;        // 0..1
    const int jb = blockIdx.x & 63;        // 0..63
    const int m0 = mb * 128;
    const int j0 = jb * 16;
    unsigned* bar = bars + 8 + mb;

    // Resident weights: 64 gate rows (4 gates x 16 j) x 1024 k bf16.
#pragma unroll
    for (int j = 0; j < 16; j++) {
        int idx = j*512 + tid, n = idx >> 7, c = idx & 127;
        int grow = (n>>4)*H2 + j0 + (n&15);
        ((uint4*)(wsh + n*516))[c] = *(const uint4*)(Whh + (size_t)grow*H2 + c*8);
    }
    if (tid < 64) bsh[tid] = bias[(tid>>4)*H2 + j0 + (tid&15)];
    __syncthreads();

    float c_reg[4] = {0.f,0.f,0.f,0.f};
    const int erow = tid >> 2, ejl = tid & 3;   // elementwise: 128 rows x 4 j/thread

    for (int t = 0; t < T_; t++) {
        const __nv_bfloat16* hp = (t == 0) ? h0 : ((t & 1) ? h2a : h2b);
        __nv_bfloat16* hn = (t & 1) ? h2b : h2a;

        // ig prefetch (16 bf16/thread)
        float pf[4][4];
#pragma unroll
        for (int s = 0; s < 4; s++) {
            int jl = ejl + s*4;
            size_t igbase = ((size_t)t*B_ + (m0 + erow)) * (size_t)G2;
#pragma unroll
            for (int gg2 = 0; gg2 < 4; gg2++)
                pf[s][gg2] = __bfloat162float(ig[igbase + gg2*H2 + j0 + jl]);
        }

        float acc[2][4][4];
#pragma unroll
        for (int a = 0; a < 2; a++)
#pragma unroll
            for (int b = 0; b < 4; b++)
#pragma unroll
                for (int c = 0; c < 4; c++) acc[a][b][c] = 0.f;

        // prefetch h slab 0 (128 rows x 64 k): 2 uint4/thread
        uint4 ph[2];
#pragma unroll
        for (int j = 0; j < 2; j++) {
            int idx = j*512 + tid, r = idx >> 3, c = idx & 7;
            ph[j] = __ldcg((const uint4*)(hp + (size_t)(m0+r)*H2 + c*8));
        }

        for (int si = 0; si < 16; si++) {
            int buf = si & 1;
#pragma unroll
            for (int j = 0; j < 2; j++) {
                int idx = j*512 + tid, r = idx >> 3, c = idx & 7;
                ((uint4*)(hs + buf*4608 + r*36))[c] = ph[j];
            }
            __syncthreads();
            if (si + 1 < 16) {
                int k0 = (si+1)*64;
#pragma unroll
                for (int j = 0; j < 2; j++) {
                    int idx = j*512 + tid, r = idx >> 3, c = idx & 7;
                    ph[j] = __ldcg((const uint4*)(hp + (size_t)(m0+r)*H2 + k0 + c*8));
                }
            }
#pragma unroll
            for (int kc = 0; kc < 2; kc++) {
                int ka = kh*16 + kc*8;          // u32 col in slab
                int kb = si*32 + ka;            // u32 col in wsh
                uint32_t af[2][4];
#pragma unroll
                for (int mt = 0; mt < 2; mt++) {
                    int r = mq*32 + mt*16;
                    af[mt][0] = hs[buf*4608 + (r+gid  )*36 + ka+tig  ];
                    af[mt][1] = hs[buf*4608 + (r+gid+8)*36 + ka+tig  ];
                    af[mt][2] = hs[buf*4608 + (r+gid  )*36 + ka+tig+4];
                    af[mt][3] = hs[buf*4608 + (r+gid+8)*36 + ka+tig+4];
                }
#pragma unroll
                for (int nt = 0; nt < 4; nt++) {
                    int br = ng*32 + nt*8 + gid;
                    uint32_t b0 = wsh[br*516 + kb+tig  ];
                    uint32_t b1 = wsh[br*516 + kb+tig+4];
#pragma unroll
                    for (int mt = 0; mt < 2; mt++)
                        mma_bf16(acc[mt][nt][0],acc[mt][nt][1],acc[mt][nt][2],acc[mt][nt][3],
                                 af[mt][0],af[mt][1],af[mt][2],af[mt][3], b0, b1);
                }
            }
        }

        // combine kh partials in gsh: kh0 stores, kh1 adds
        if (kh == 0) {
#pragma unroll
            for (int mt = 0; mt < 2; mt++) {
                int rb = mq*32 + mt*16;
#pragma unroll
                for (int nt = 0; nt < 4; nt++) {
                    int col = ng*32 + nt*8 + 2*tig;
                    gsh[(rb+gid  )*65 + col  ] = acc[mt][nt][0];
                    gsh[(rb+gid  )*65 + col+1] = acc[mt][nt][1];
                    gsh[(rb+gid+8)*65 + col  ] = acc[mt][nt][2];
                    gsh[(rb+gid+8)*65 + col+1] = acc[mt][nt][3];
                }
            }
        }
        __syncthreads();
        if (kh == 1) {
#pragma unroll
            for (int mt = 0; mt < 2; mt++) {
                int rb = mq*32 + mt*16;
#pragma unroll
                for (int nt = 0; nt < 4; nt++) {
                    int col = ng*32 + nt*8 + 2*tig;
                    gsh[(rb+gid  )*65 + col  ] += acc[mt][nt][0];
                    gsh[(rb+gid  )*65 + col+1] += acc[mt][nt][1];
                    gsh[(rb+gid+8)*65 + col  ] += acc[mt][nt][2];
                    gsh[(rb+gid+8)*65 + col+1] += acc[mt][nt][3];
                }
            }
        }
        __syncthreads();

        // elementwise: gsh col = gate*16 + jl
#pragma unroll
        for (int s = 0; s < 4; s++) {
            int jl = ejl + s*4;
            float gi = gsh[erow*65 +      jl] + pf[s][0] + bsh[      jl];
            float gf = gsh[erow*65 + 16 + jl] + pf[s][1] + bsh[ 16 + jl];
            float gg = gsh[erow*65 + 32 + jl] + pf[s][2] + bsh[ 32 + jl];
            float go = gsh[erow*65 + 48 + jl] + pf[s][3] + bsh[ 48 + jl];
            float cn = sigm_ap(gf)*c_reg[s] + sigm_ap(gi)*tanh_ap(gg);
            c_reg[s] = cn;
            hn[(size_t)(m0+erow)*H2 + j0 + jl] = __float2bfloat16(sigm_ap(go)*tanh_ap(cn));
        }

        group_barrier(bar, 64u*(unsigned)(t+1), tid);
    }
}

__global__ void classifier_kernel(const __nv_bfloat16* __restrict__ h,
                                  const float* __restrict__ Wl,
                                  const float* __restrict__ bl, float* __restrict__ out)
{
    int wid = (blockIdx.x * blockDim.x + threadIdx.x) >> 5;
    int lane = threadIdx.x & 31;
    if (wid >= B_) return;
    const __nv_bfloat16* hb = h + (size_t)wid * H2;
    float s0 = 0.f, s1 = 0.f;
    for (int j = lane; j < H2; j += 32) {
        float hv = __bfloat162float(hb[j]);
        s0 += hv * Wl[j];
        s1 += hv * Wl[H2 + j];
    }
#pragma unroll
    for (int o = 16; o > 0; o >>= 1) {
        s0 += __shfl_down_sync(0xFFFFFFFFu, s0, o);
        s1 += __shfl_down_sync(0xFFFFFFFFu, s1, o);
    }
    if (lane == 0) {
        out[wid*2+0] = sigm_ex(s0 + bl[0]);
        out[wid*2+1] = sigm_ex(s1 + bl[1]);
    }
}

extern "C" void kernel_launch(void* const* d_in, const int* in_sizes, int n_in,
                              void* d_out, int out_size)
{
    (void)in_sizes; (void)n_in; (void)out_size;
    const float* x     = (const float*)d_in[0];
    const float* Wf_ih = (const float*)d_in[1];
    const float* Wf_hh = (const float*)d_in[2];
    const float* bf    = (const float*)d_in[3];
    const float* Wb_ih = (const float*)d_in[4];
    const float* Wb_hh = (const float*)d_in[5];
    const float* bb    = (const float*)d_in[6];
    const float* Ws_ih = (const float*)d_in[7];
    const float* Ws_hh = (const float*)d_in[8];
    const float* bs    = (const float*)d_in[9];
    const float* Wl    = (const float*)d_in[10];
    const float* bl    = (const float*)d_in[11];
    float* out = (float*)d_out;

    unsigned* p_bars;
    __nv_bfloat16 *p_igf, *p_igb, *p_igs;
    __nv_bfloat16 *p_xb, *p_comb, *p_zero, *p_h2a, *p_h2b;
    __nv_bfloat16 *p_wfih, *p_wbih, *p_wsih, *p_wfhh, *p_wbhh, *p_wshh;
    cudaGetSymbolAddress((void**)&p_igf,  g_igf);
    cudaGetSymbolAddress((void**)&p_igb,  g_igb);
    cudaGetSymbolAddress((void**)&p_igs,  g_igs);
    cudaGetSymbolAddress((void**)&p_bars, g_bars);
    cudaGetSymbolAddress((void**)&p_xb,   g_xb);
    cudaGetSymbolAddress((void**)&p_comb, g_comb);
    cudaGetSymbolAddress((void**)&p_zero, g_zero);
    cudaGetSymbolAddress((void**)&p_h2a,  g_h2a);
    cudaGetSymbolAddress((void**)&p_h2b,  g_h2b);
    cudaGetSymbolAddress((void**)&p_wfih, g_wfih);
    cudaGetSymbolAddress((void**)&p_wbih, g_wbih);
    cudaGetSymbolAddress((void**)&p_wsih, g_wsih);
    cudaGetSymbolAddress((void**)&p_wfhh, g_wfhh);
    cudaGetSymbolAddress((void**)&p_wbhh, g_wbhh);
    cudaGetSymbolAddress((void**)&p_wshh, g_wshh);

    cudaFuncSetAttribute(lstm_scan1, cudaFuncAttributeMaxDynamicSharedMemorySize, S1_SMEM);
    cudaFuncSetAttribute(lstm_scan2, cudaFuncAttributeMaxDynamicSharedMemorySize, S2_SMEM);

    cudaMemsetAsync(p_zero, 0, (size_t)B_*H2*sizeof(__nv_bfloat16));
    cudaMemsetAsync(p_bars, 0, 16*sizeof(unsigned));

    Seg7 sp;
    sp.seg[0] = { x,     p_xb,   B_*T_*D_ };
    sp.seg[1] = { Wf_ih, p_wfih, G1*D_ };
    sp.seg[2] = { Wb_ih, p_wbih, G1*D_ };
    sp.seg[3] = { Ws_ih, p_wsih, G2*(2*H1) };
    sp.seg[4] = { Wf_hh, p_wfhh, G1*H1 };
    sp.seg[5] = { Wb_hh, p_wbhh, G1*H1 };
    sp.seg[6] = { Ws_hh, p_wshh, G2*H2 };
    f2bf_all<<<1184, 256>>>(sp);

    gemm_bf16_nt<<<dim3(G1/128, (B_*T_)/128), 256>>>(p_xb, p_wfih, p_igf, B_*T_, G1, D_, 1);
    gemm_bf16_nt<<<dim3(G1/128, (B_*T_)/128), 256>>>(p_xb, p_wbih, p_igb, B_*T_, G1, D_, 2);

    lstm_scan1<<<128, 512, S1_SMEM>>>(p_wfhh, p_wbhh, bf, bb, p_igf, p_igb,
                                      p_zero, p_comb, p_bars);

    gemm_bf16_nt<<<dim3(G2/128, (B_*T_)/128), 256>>>(p_comb, p_wsih, p_igs, B_*T_, G2, 2*H1, 0);

    lstm_scan2<<<128, 512, S2_SMEM>>>(p_wshh, bs, p_igs, p_zero, p_h2a, p_h2b, p_bars);

    classifier_kernel<<<32, 256>>>(p_h2b, Wl, bl, out);
}

// round 17
// speedup vs baseline: 1.0827x; 1.0827x over previous
#include <cuda_runtime.h>
#include <cuda_bf16.h>
#include <cstdint>
#include <cmath>

#define B_  256
#define T_  128
#define D_  256
#define H1  512
#define G1  (4*H1)
#define H2  1024
#define G2  (4*H2)

// scratch
__device__ unsigned g_bars[16];
__device__ __nv_bfloat16 g_igf [(size_t)T_*B_*G1];
__device__ __nv_bfloat16 g_igb [(size_t)T_*B_*G1];
__device__ __nv_bfloat16 g_igs [(size_t)T_*B_*G2];
__device__ __nv_bfloat16 g_xb  [(size_t)B_*T_*D_];
__device__ __nv_bfloat16 g_comb[(size_t)T_*B_*(2*H1)];
__device__ __nv_bfloat16 g_zero[B_*H2];
__device__ __nv_bfloat16 g_h2a [B_*H2];
__device__ __nv_bfloat16 g_h2b [B_*H2];
__device__ __nv_bfloat16 g_wfih[(size_t)G1*D_];
__device__ __nv_bfloat16 g_wbih[(size_t)G1*D_];
__device__ __nv_bfloat16 g_wsih[(size_t)G2*(2*H1)];
__device__ __nv_bfloat16 g_wfhh[(size_t)G1*H1];
__device__ __nv_bfloat16 g_wbhh[(size_t)G1*H1];
__device__ __nv_bfloat16 g_wshh[(size_t)G2*H2];

__device__ __forceinline__ void mma_bf16(float& d0, float& d1, float& d2, float& d3,
                                         uint32_t a0, uint32_t a1, uint32_t a2, uint32_t a3,
                                         uint32_t b0, uint32_t b1) {
    asm volatile("mma.sync.aligned.m16n8k16.row.col.f32.bf16.bf16.f32 "
        "{%0,%1,%2,%3}, {%4,%5,%6,%7}, {%8,%9}, {%0,%1,%2,%3};\n"
        : "+f"(d0), "+f"(d1), "+f"(d2), "+f"(d3)
        : "r"(a0), "r"(a1), "r"(a2), "r"(a3), "r"(b0), "r"(b1));
}
__device__ __forceinline__ float tanh_ap(float x) {
    float y; asm("tanh.approx.f32 %0, %1;" : "=f"(y) : "f"(x)); return y;
}
__device__ __forceinline__ float sigm_ap(float x) { return 0.5f * tanh_ap(0.5f * x) + 0.5f; }
__device__ __forceinline__ float sigm_ex(float x) { return 1.0f / (1.0f + expf(-x)); }

// Release/acquire group barrier: call with all threads; h-stores must precede.
__device__ __forceinline__ void group_barrier(unsigned* bar, unsigned target, int tid) {
    __syncthreads();
    if (tid == 0) {
        asm volatile("red.release.gpu.global.add.u32 [%0], %1;" :: "l"(bar), "r"(1u) : "memory");
        unsigned v;
        while (true) {
            asm volatile("ld.acquire.gpu.global.u32 %0, [%1];" : "=r"(v) : "l"(bar) : "memory");
            if ((int)(v - target) >= 0) break;
            __nanosleep(32);
        }
    }
    __syncthreads();
}

// ---------------------------------------------------------------------------
// Fused, vectorized fp32->bf16 conversion (float4 in, 2x bf16x2 out).
// All segment sizes divisible by 4.
// ---------------------------------------------------------------------------
struct SegT { const float* s; __nv_bfloat16* d; int n; };
struct Seg7 { SegT seg[7]; };

__global__ void f2bf_all(Seg7 p) {
    int stride = gridDim.x * blockDim.x;
    int base = blockIdx.x * blockDim.x + threadIdx.x;
#pragma unroll
    for (int k = 0; k < 7; k++) {
        const float4* s = (const float4*)p.seg[k].s;
        __nv_bfloat162* d = (__nv_bfloat162*)p.seg[k].d;
        int n4 = p.seg[k].n >> 2;
        for (int i = base; i < n4; i += stride) {
            float4 v = s[i];
            __nv_bfloat162 lo, hi;
            lo.x = __float2bfloat16(v.x); lo.y = __float2bfloat16(v.y);
            hi.x = __float2bfloat16(v.z); hi.y = __float2bfloat16(v.w);
            d[2*i]   = lo;
            d[2*i+1] = hi;
        }
    }
}

// ---------------------------------------------------------------------------
// bf16 GEMM, bf16 output, double-buffered smem (1 sync per k-tile).
// BM=128, BN=128, BK=32; 256 thr; warps 2x4; warp tile 64x32.
// ---------------------------------------------------------------------------
__global__ void __launch_bounds__(256, 2) gemm_bf16_nt(
    const __nv_bfloat16* __restrict__ A, const __nv_bfloat16* __restrict__ W,
    __nv_bfloat16* __restrict__ out, int M, int N, int K, int remap)
{
    __shared__ uint32_t As[2][128][20];
    __shared__ uint32_t Bs[2][128][20];
    const int tid = threadIdx.x, lane = tid & 31, warp = tid >> 5;
    const int gid = lane >> 2, tig = lane & 3;
    const int wm = warp >> 2, wn = warp & 3;
    const int bm0 = blockIdx.y * 128, bn0 = blockIdx.x * 128;

    float acc[4][4][4];
#pragma unroll
    for (int a = 0; a < 4; a++)
#pragma unroll
        for (int b = 0; b < 4; b++)
#pragma unroll
            for (int c = 0; c < 4; c++) acc[a][b][c] = 0.f;

    const int kIters = K / 32;
    uint4 pa[2], pb[2];
#pragma unroll
    for (int j = 0; j < 2; j++) { int i = tid + j*256, r = i>>2, c = i&3;
        pa[j] = *(const uint4*)(A + (size_t)(bm0+r)*K + c*8);
        pb[j] = *(const uint4*)(W + (size_t)(bn0+r)*K + c*8); }

    for (int kt = 0; kt < kIters; kt++) {
        int buf = kt & 1;
#pragma unroll
        for (int j = 0; j < 2; j++) { int i = tid + j*256, r = i>>2, c = i&3;
            As[buf][r][c*4+0]=pa[j].x; As[buf][r][c*4+1]=pa[j].y;
            As[buf][r][c*4+2]=pa[j].z; As[buf][r][c*4+3]=pa[j].w;
            Bs[buf][r][c*4+0]=pb[j].x; Bs[buf][r][c*4+1]=pb[j].y;
            Bs[buf][r][c*4+2]=pb[j].z; Bs[buf][r][c*4+3]=pb[j].w; }
        __syncthreads();
        if (kt + 1 < kIters) {
            int k0 = (kt+1)*32;
#pragma unroll
            for (int j = 0; j < 2; j++) { int i = tid + j*256, r = i>>2, c = i&3;
                pa[j] = *(const uint4*)(A + (size_t)(bm0+r)*K + k0 + c*8);
                pb[j] = *(const uint4*)(W + (size_t)(bn0+r)*K + k0 + c*8); }
        }
#pragma unroll
        for (int kc = 0; kc < 2; kc++) {
            uint32_t af[4][4];
#pragma unroll
            for (int mt = 0; mt < 4; mt++) {
                int r = wm*64 + mt*16;
                af[mt][0] = As[buf][r+gid  ][kc*8+tig  ];
                af[mt][1] = As[buf][r+gid+8][kc*8+tig  ];
                af[mt][2] = As[buf][r+gid  ][kc*8+tig+4];
                af[mt][3] = As[buf][r+gid+8][kc*8+tig+4];
            }
#pragma unroll
            for (int nt = 0; nt < 4; nt++) {
                int cc = wn*32 + nt*8;
                uint32_t b0 = Bs[buf][cc+gid][kc*8+tig  ];
                uint32_t b1 = Bs[buf][cc+gid][kc*8+tig+4];
#pragma unroll
                for (int mt = 0; mt < 4; mt++)
                    mma_bf16(acc[mt][nt][0],acc[mt][nt][1],acc[mt][nt][2],acc[mt][nt][3],
                             af[mt][0],af[mt][1],af[mt][2],af[mt][3], b0, b1);
            }
        }
    }
#pragma unroll
    for (int mt = 0; mt < 4; mt++)
#pragma unroll
        for (int half = 0; half < 2; half++) {
            int m = bm0 + wm*64 + mt*16 + gid + half*8;
            int orow;
            if (remap == 0) orow = m;
            else { int t = m % T_, b = m / T_;
                   orow = ((remap == 1) ? t : (T_-1-t)) * B_ + b; }
            __nv_bfloat16* op = out + (size_t)orow*N + bn0 + wn*32 + 2*tig;
#pragma unroll
            for (int nt = 0; nt < 4; nt++) {
                __nv_bfloat162 v;
                v.x = __float2bfloat16(acc[mt][nt][half*2+0]);
                v.y = __float2bfloat16(acc[mt][nt][half*2+1]);
                *(__nv_bfloat162*)(op + nt*8) = v;
            }
        }
}

// ---------------------------------------------------------------------------
// Layer-1 persistent scan (R13-proven) + release/acquire barrier.
// grid = 128 = dir(2) x mb(4) x jt(16); 512 thr; K-split warps.
// ---------------------------------------------------------------------------
#define S1_ASH (128*260)
#define S1_SMEM (((128*260)+(64*260))*4)

__global__ void __launch_bounds__(512, 1) lstm_scan1(
    const __nv_bfloat16* __restrict__ Whh_f, const __nv_bfloat16* __restrict__ Whh_b,
    const float* __restrict__ bias_f, const float* __restrict__ bias_b,
    const __nv_bfloat16* __restrict__ igf, const __nv_bfloat16* __restrict__ igb,
    const __nv_bfloat16* __restrict__ h0, __nv_bfloat16* __restrict__ hist,
    unsigned* __restrict__ bars)
{
    extern __shared__ uint32_t dsm[];
    uint32_t* wsh = dsm;
    uint32_t* ash = dsm + S1_ASH;
    float*    gsh = (float*)(dsm + S1_ASH);   // [2][64][129]
    __shared__ float bsh[128];

    const int tid = threadIdx.x, lane = tid & 31, warp = tid >> 5;
    const int gid = lane >> 2, tig = lane & 3;
    const int kh = warp >> 3, mq = (warp >> 2) & 1, g = warp & 3;

    const int dir = blockIdx.x >> 6;
    const int rem = blockIdx.x & 63;
    const int m0  = (rem >> 4) * 64;
    const int j0  = (rem & 15) * 32;
    unsigned* bar = bars + (dir*4 + (rem >> 4));

    const __nv_bfloat16* Whh = dir ? Whh_b : Whh_f;
    const float* bias = dir ? bias_b : bias_f;
    const __nv_bfloat16* ig = dir ? igb : igf;
    const int hstride = 2*H1, hdiroff = dir*H1;

#pragma unroll
    for (int j = 0; j < 16; j++) {
        int idx = j*512 + tid, n = idx >> 6, c = idx & 63;
        int grow = (n>>5)*H1 + j0 + (n&31);
        ((uint4*)(wsh + n*260))[c] = *(const uint4*)(Whh + (size_t)grow*H1 + c*8);
    }
    if (tid < 128) bsh[tid] = bias[(tid>>5)*H1 + j0 + (tid&31)];
    __syncthreads();

    float c_reg[4] = {0.f,0.f,0.f,0.f};
    const int erow = tid >> 5, ejj = tid & 31;
    const int ej = j0 + ejj;

    for (int t = 0; t < T_; t++) {
        const __nv_bfloat16* hp = (t == 0) ? h0 : hist + (size_t)(t-1)*B_*(2*H1);
        __nv_bfloat16* hn = hist + (size_t)t*B_*(2*H1);

        float pf[4][4];
#pragma unroll
        for (int s = 0; s < 4; s++) {
            int b = m0 + erow + s*16;
            size_t igbase = ((size_t)t*B_ + b) * (size_t)G1;
#pragma unroll
            for (int gg2 = 0; gg2 < 4; gg2++)
                pf[s][gg2] = __bfloat162float(ig[igbase + gg2*H1 + ej]);
        }

#pragma unroll
        for (int j = 0; j < 8; j++) {
            int idx = j*512 + tid, r = idx >> 6, c = idx & 63;
            uint4 v = __ldcg((const uint4*)(hp + (size_t)(m0+r)*hstride + hdiroff + c*8));
            ((uint4*)(ash + r*260))[c] = v;
        }
        __syncthreads();

        float acc[2][4][4];
#pragma unroll
        for (int a = 0; a < 2; a++)
#pragma unroll
            for (int b = 0; b < 4; b++)
#pragma unroll
                for (int c = 0; c < 4; c++) acc[a][b][c] = 0.f;

#pragma unroll 4
        for (int kc = 0; kc < 16; kc++) {
            int kb = kh*128 + kc*8;
            uint32_t af[2][4];
#pragma unroll
            for (int mt = 0; mt < 2; mt++) {
                int r = mq*32 + mt*16;
                af[mt][0] = ash[(r+gid  )*260 + kb+tig  ];
                af[mt][1] = ash[(r+gid+8)*260 + kb+tig  ];
                af[mt][2] = ash[(r+gid  )*260 + kb+tig+4];
                af[mt][3] = ash[(r+gid+8)*260 + kb+tig+4];
            }
#pragma unroll
            for (int nt = 0; nt < 4; nt++) {
                int br = g*32 + nt*8 + gid;
                uint32_t b0 = wsh[br*260 + kb+tig  ];
                uint32_t b1 = wsh[br*260 + kb+tig+4];
#pragma unroll
                for (int mt = 0; mt < 2; mt++)
                    mma_bf16(acc[mt][nt][0],acc[mt][nt][1],acc[mt][nt][2],acc[mt][nt][3],
                             af[mt][0],af[mt][1],af[mt][2],af[mt][3], b0, b1);
            }
        }
        __syncthreads();   // mmas done -> overwrite ash with gsh planes

        float* gp = gsh + kh*64*129;
#pragma unroll
        for (int mt = 0; mt < 2; mt++) {
            int rb = mq*32 + mt*16;
#pragma unroll
            for (int nt = 0; nt < 4; nt++) {
                int col = g*32 + nt*8 + 2*tig;
                gp[(rb+gid  )*129 + col  ] = acc[mt][nt][0];
                gp[(rb+gid  )*129 + col+1] = acc[mt][nt][1];
                gp[(rb+gid+8)*129 + col  ] = acc[mt][nt][2];
                gp[(rb+gid+8)*129 + col+1] = acc[mt][nt][3];
            }
        }
        __syncthreads();

#pragma unroll
        for (int s = 0; s < 4; s++) {
            int row = erow + s*16;
            int b = m0 + row;
            float gi = gsh[row*129 +      ejj] + gsh[64*129 + row*129 +      ejj] + pf[s][0] + bsh[      ejj];
            float gf = gsh[row*129 + 32 + ejj] + gsh[64*129 + row*129 + 32 + ejj] + pf[s][1] + bsh[ 32 + ejj];
            float gg = gsh[row*129 + 64 + ejj] + gsh[64*129 + row*129 + 64 + ejj] + pf[s][2] + bsh[ 64 + ejj];
            float go = gsh[row*129 + 96 + ejj] + gsh[64*129 + row*129 + 96 + ejj] + pf[s][3] + bsh[ 96 + ejj];
            float cn = sigm_ap(gf)*c_reg[s] + sigm_ap(gi)*tanh_ap(gg);
            c_reg[s] = cn;
            hn[(size_t)b*hstride + hdiroff + ej] = __float2bfloat16(sigm_ap(go)*tanh_ap(cn));
        }

        group_barrier(bar, 16u*(unsigned)(t+1), tid);
    }
}

// ---------------------------------------------------------------------------
// Layer-2 persistent scan (R13-proven structure): h resident per step,
// weights double-buffered in 8 x 128-k slabs; 4 barrier groups of 32.
// grid = 128 = mb(4) x jt(32); 512 thr; K-split warps.
// dyn smem (u32): ash[64][516] (gsh[2] planes alias) | bs[2][128][68].
// ---------------------------------------------------------------------------
#define S2_BS  (64*516)
#define S2_SMEM (((64*516)+(2*128*68))*4)

__global__ void __launch_bounds__(512, 1) lstm_scan2(
    const __nv_bfloat16* __restrict__ Whh,
    const float* __restrict__ bias, const __nv_bfloat16* __restrict__ ig,
    const __nv_bfloat16* __restrict__ h0,
    __nv_bfloat16* __restrict__ h2a, __nv_bfloat16* __restrict__ h2b,
    unsigned* __restrict__ bars)
{
    extern __shared__ uint32_t dsm[];
    uint32_t* ash = dsm;
    float*    gsh = (float*)dsm;          // [2][64][129]
    uint32_t* bs  = dsm + S2_BS;          // [2][128][68]
    __shared__ float bsh[128];

    const int tid = threadIdx.x, lane = tid & 31, warp = tid >> 5;
    const int gid = lane >> 2, tig = lane & 3;
    const int kh = warp >> 3, mq = (warp >> 2) & 1, g = warp & 3;

    const int m0 = (blockIdx.x >> 5) * 64;
    const int j0 = (blockIdx.x & 31) * 32;
    unsigned* bar = bars + 8 + (blockIdx.x >> 5);

    if (tid < 128) bsh[tid] = bias[(tid>>5)*H2 + j0 + (tid&31)];
    __syncthreads();

    float c_reg[4] = {0.f,0.f,0.f,0.f};
    const int erow = tid >> 5, ejj = tid & 31;
    const int ej = j0 + ejj;

    for (int t = 0; t < T_; t++) {
        const __nv_bfloat16* hp = (t == 0) ? h0 : ((t & 1) ? h2a : h2b);
        __nv_bfloat16* hn = (t & 1) ? h2b : h2a;

        // ig prefetch
        float pf[4][4];
#pragma unroll
        for (int s = 0; s < 4; s++) {
            int b = m0 + erow + s*16;
            size_t igbase = ((size_t)t*B_ + b) * (size_t)G2;
#pragma unroll
            for (int gg2 = 0; gg2 < 4; gg2++)
                pf[s][gg2] = __bfloat162float(ig[igbase + gg2*H2 + ej]);
        }

        // full h -> smem: 64 rows x 512 u32
#pragma unroll
        for (int j = 0; j < 16; j++) {
            int idx = j*512 + tid, r = idx >> 7, c = idx & 127;
            uint4 v = __ldcg((const uint4*)(hp + (size_t)(m0+r)*H2 + c*8));
            ((uint4*)(ash + r*516))[c] = v;
        }

        // prefetch weight slab 0 (128 rows x 128 bf16)
        uint4 pb[4];
#pragma unroll
        for (int j = 0; j < 4; j++) {
            int idx = j*512 + tid, n = idx >> 4, c = idx & 15;
            int grow = (n>>5)*H2 + j0 + (n&31);
            pb[j] = *(const uint4*)(Whh + (size_t)grow*H2 + c*8);
        }
        __syncthreads();   // ash ready + bs free

        float acc[2][4][4];
#pragma unroll
        for (int a = 0; a < 2; a++)
#pragma unroll
            for (int b = 0; b < 4; b++)
#pragma unroll
                for (int c = 0; c < 4; c++) acc[a][b][c] = 0.f;

        for (int si = 0; si < 8; si++) {
            int buf = si & 1;
#pragma unroll
            for (int j = 0; j < 4; j++) {
                int idx = j*512 + tid, n = idx >> 4, c = idx & 15;
                ((uint4*)(bs + buf*128*68 + n*68))[c] = pb[j];
            }
            __syncthreads();
            if (si + 1 < 8) {
                int k0 = (si+1)*128;
#pragma unroll
                for (int j = 0; j < 4; j++) {
                    int idx = j*512 + tid, n = idx >> 4, c = idx & 15;
                    int grow = (n>>5)*H2 + j0 + (n&31);
                    pb[j] = *(const uint4*)(Whh + (size_t)grow*H2 + k0 + c*8);
                }
            }
#pragma unroll
            for (int kc = 0; kc < 4; kc++) {
                int kba = si*64 + kh*32 + kc*8;   // ash u32 col
                int kbb = kh*32 + kc*8;           // bs u32 col
                uint32_t af[2][4];
#pragma unroll
                for (int mt = 0; mt < 2; mt++) {
                    int r = mq*32 + mt*16;
                    af[mt][0] = ash[(r+gid  )*516 + kba+tig  ];
                    af[mt][1] = ash[(r+gid+8)*516 + kba+tig  ];
                    af[mt][2] = ash[(r+gid  )*516 + kba+tig+4];
                    af[mt][3] = ash[(r+gid+8)*516 + kba+tig+4];
                }
#pragma unroll
                for (int nt = 0; nt < 4; nt++) {
                    int br = g*32 + nt*8 + gid;
                    uint32_t b0 = bs[buf*128*68 + br*68 + kbb+tig  ];
                    uint32_t b1 = bs[buf*128*68 + br*68 + kbb+tig+4];
#pragma unroll
                    for (int mt = 0; mt < 2; mt++)
                        mma_bf16(acc[mt][nt][0],acc[mt][nt][1],acc[mt][nt][2],acc[mt][nt][3],
                                 af[mt][0],af[mt][1],af[mt][2],af[mt][3], b0, b1);
                }
            }
            // no sync: next si stores into the other buffer
        }
        __syncthreads();   // mmas done -> overwrite ash with gsh planes

        float* gp = gsh + kh*64*129;
#pragma unroll
        for (int mt = 0; mt < 2; mt++) {
            int rb = mq*32 + mt*16;
#pragma unroll
            for (int nt = 0; nt < 4; nt++) {
                int col = g*32 + nt*8 + 2*tig;
                gp[(rb+gid  )*129 + col  ] = acc[mt][nt][0];
                gp[(rb+gid  )*129 + col+1] = acc[mt][nt][1];
                gp[(rb+gid+8)*129 + col  ] = acc[mt][nt][2];
                gp[(rb+gid+8)*129 + col+1] = acc[mt][nt][3];
            }
        }
        __syncthreads();

#pragma unroll
        for (int s = 0; s < 4; s++) {
            int row = erow + s*16;
            int b = m0 + row;
            float gi = gsh[row*129 +      ejj] + gsh[64*129 + row*129 +      ejj] + pf[s][0] + bsh[      ejj];
            float gf = gsh[row*129 + 32 + ejj] + gsh[64*129 + row*129 + 32 + ejj] + pf[s][1] + bsh[ 32 + ejj];
            float gg = gsh[row*129 + 64 + ejj] + gsh[64*129 + row*129 + 64 + ejj] + pf[s][2] + bsh[ 64 + ejj];
            float go = gsh[row*129 + 96 + ejj] + gsh[64*129 + row*129 + 96 + ejj] + pf[s][3] + bsh[ 96 + ejj];
            float cn = sigm_ap(gf)*c_reg[s] + sigm_ap(gi)*tanh_ap(gg);
            c_reg[s] = cn;
            hn[(size_t)b*H2 + ej] = __float2bfloat16(sigm_ap(go)*tanh_ap(cn));
        }

        group_barrier(bar, 32u*(unsigned)(t+1), tid);
    }
}

__global__ void classifier_kernel(const __nv_bfloat16* __restrict__ h,
                                  const float* __restrict__ Wl,
                                  const float* __restrict__ bl, float* __restrict__ out)
{
    int wid = (blockIdx.x * blockDim.x + threadIdx.x) >> 5;
    int lane = threadIdx.x & 31;
    if (wid >= B_) return;
    const __nv_bfloat16* hb = h + (size_t)wid * H2;
    float s0 = 0.f, s1 = 0.f;
    for (int j = lane; j < H2; j += 32) {
        float hv = __bfloat162float(hb[j]);
        s0 += hv * Wl[j];
        s1 += hv * Wl[H2 + j];
    }
#pragma unroll
    for (int o = 16; o > 0; o >>= 1) {
        s0 += __shfl_down_sync(0xFFFFFFFFu, s0, o);
        s1 += __shfl_down_sync(0xFFFFFFFFu, s1, o);
    }
    if (lane == 0) {
        out[wid*2+0] = sigm_ex(s0 + bl[0]);
        out[wid*2+1] = sigm_ex(s1 + bl[1]);
    }
}

extern "C" void kernel_launch(void* const* d_in, const int* in_sizes, int n_in,
                              void* d_out, int out_size)
{
    (void)in_sizes; (void)n_in; (void)out_size;
    const float* x     = (const float*)d_in[0];
    const float* Wf_ih = (const float*)d_in[1];
    const float* Wf_hh = (const float*)d_in[2];
    const float* bf    = (const float*)d_in[3];
    const float* Wb_ih = (const float*)d_in[4];
    const float* Wb_hh = (const float*)d_in[5];
    const float* bb    = (const float*)d_in[6];
    const float* Ws_ih = (const float*)d_in[7];
    const float* Ws_hh = (const float*)d_in[8];
    const float* bs    = (const float*)d_in[9];
    const float* Wl    = (const float*)d_in[10];
    const float* bl    = (const float*)d_in[11];
    float* out = (float*)d_out;

    unsigned* p_bars;
    __nv_bfloat16 *p_igf, *p_igb, *p_igs;
    __nv_bfloat16 *p_xb, *p_comb, *p_zero, *p_h2a, *p_h2b;
    __nv_bfloat16 *p_wfih, *p_wbih, *p_wsih, *p_wfhh, *p_wbhh, *p_wshh;
    cudaGetSymbolAddress((void**)&p_igf,  g_igf);
    cudaGetSymbolAddress((void**)&p_igb,  g_igb);
    cudaGetSymbolAddress((void**)&p_igs,  g_igs);
    cudaGetSymbolAddress((void**)&p_bars, g_bars);
    cudaGetSymbolAddress((void**)&p_xb,   g_xb);
    cudaGetSymbolAddress((void**)&p_comb, g_comb);
    cudaGetSymbolAddress((void**)&p_zero, g_zero);
    cudaGetSymbolAddress((void**)&p_h2a,  g_h2a);
    cudaGetSymbolAddress((void**)&p_h2b,  g_h2b);
    cudaGetSymbolAddress((void**)&p_wfih, g_wfih);
    cudaGetSymbolAddress((void**)&p_wbih, g_wbih);
    cudaGetSymbolAddress((void**)&p_wsih, g_wsih);
    cudaGetSymbolAddress((void**)&p_wfhh, g_wfhh);
    cudaGetSymbolAddress((void**)&p_wbhh, g_wbhh);
    cudaGetSymbolAddress((void**)&p_wshh, g_wshh);

    cudaFuncSetAttribute(lstm_scan1, cudaFuncAttributeMaxDynamicSharedMemorySize, S1_SMEM);
    cudaFuncSetAttribute(lstm_scan2, cudaFuncAttributeMaxDynamicSharedMemorySize, S2_SMEM);

    cudaMemsetAsync(p_zero, 0, (size_t)B_*H2*sizeof(__nv_bfloat16));
    cudaMemsetAsync(p_bars, 0, 16*sizeof(unsigned));

    Seg7 sp;
    sp.seg[0] = { x,     p_xb,   B_*T_*D_ };
    sp.seg[1] = { Wf_ih, p_wfih, G1*D_ };
    sp.seg[2] = { Wb_ih, p_wbih, G1*D_ };
    sp.seg[3] = { Ws_ih, p_wsih, G2*(2*H1) };
    sp.seg[4] = { Wf_hh, p_wfhh, G1*H1 };
    sp.seg[5] = { Wb_hh, p_wbhh, G1*H1 };
    sp.seg[6] = { Ws_hh, p_wshh, G2*H2 };
    f2bf_all<<<1184, 256>>>(sp);

    gemm_bf16_nt<<<dim3(G1/128, (B_*T_)/128), 256>>>(p_xb, p_wfih, p_igf, B_*T_, G1, D_, 1);
    gemm_bf16_nt<<<dim3(G1/128, (B_*T_)/128), 256>>>(p_xb, p_wbih, p_igb, B_*T_, G1, D_, 2);

    lstm_scan1<<<128, 512, S1_SMEM>>>(p_wfhh, p_wbhh, bf, bb, p_igf, p_igb,
                                      p_zero, p_comb, p_bars);

    gemm_bf16_nt<<<dim3(G2/128, (B_*T_)/128), 256>>>(p_comb, p_wsih, p_igs, B_*T_, G2, 2*H1, 0);

    lstm_scan2<<<128, 512, S2_SMEM>>>(p_wshh, bs, p_igs, p_zero, p_h2a, p_h2b, p_bars);

    classifier_kernel<<<32, 256>>>(p_h2b, Wl, bl, out);
}